// round 2
// baseline (speedup 1.0000x reference)
#include <cuda_runtime.h>

// Problem constants (from reference): NP=44 tiny MLPs, B=400000 batch.
#define NP_ 44
#define B_  400000
#define B4_ (B_ / 4)          // 100000 float4 per l

// Precomputed per-l scale for x>0 (index 2l) and x<0 (index 2l+1).
__device__ float g_scales[NP_ * 2];

// Collapse the 1->4->8->4->1 ReLU MLP into two scalars per l.
// For scalar input x, every activation is coeff*x; the ReLU mask depends only
// on sign(x): keep positive coefficients when x>0, negative when x<0.
__global__ void precompute_scales(const float* __restrict__ w1,   // (NP,4,1)
                                  const float* __restrict__ w2,   // (NP,8,4)
                                  const float* __restrict__ w3,   // (NP,4,8)
                                  const float* __restrict__ w4) { // (NP,1,4)
    int l = blockIdx.x * blockDim.x + threadIdx.x;
    if (l >= NP_) return;
    const float* W1 = w1 + l * 4;
    const float* W2 = w2 + l * 32;
    const float* W3 = w3 + l * 32;
    const float* W4 = w4 + l * 4;

    #pragma unroll
    for (int s = 0; s < 2; ++s) {
        const bool pos = (s == 0);
        float a[4];
        #pragma unroll
        for (int i = 0; i < 4; ++i) {
            float w = W1[i];
            a[i] = (pos ? (w > 0.0f) : (w < 0.0f)) ? w : 0.0f;
        }
        float b[8];
        #pragma unroll
        for (int j = 0; j < 8; ++j) {
            float t = 0.0f;
            #pragma unroll
            for (int i = 0; i < 4; ++i) t += W2[j * 4 + i] * a[i];
            b[j] = (pos ? (t > 0.0f) : (t < 0.0f)) ? t : 0.0f;
        }
        float c[4];
        #pragma unroll
        for (int i = 0; i < 4; ++i) {
            float t = 0.0f;
            #pragma unroll
            for (int j = 0; j < 8; ++j) t += W3[i * 8 + j] * b[j];
            c[i] = (pos ? (t > 0.0f) : (t < 0.0f)) ? t : 0.0f;
        }
        float out = 0.0f;
        #pragma unroll
        for (int i = 0; i < 4; ++i) out += W4[i] * c[i];
        g_scales[2 * l + s] = out;
    }
}

// Streaming kernel: out = (x>0 ? s_pos : s_neg) * x, vectorized float4.
__global__ __launch_bounds__(256) void apply_scales(
    const float4* __restrict__ X, float4* __restrict__ O) {
    const int l = blockIdx.y;
    const int i = blockIdx.x * blockDim.x + threadIdx.x;
    if (i >= B4_) return;

    const float sp = g_scales[2 * l];
    const float sn = g_scales[2 * l + 1];

    const long idx = (long)l * B4_ + i;
    float4 x = X[idx];
    float4 o;
    o.x = (x.x > 0.0f ? sp : sn) * x.x;
    o.y = (x.y > 0.0f ? sp : sn) * x.y;
    o.z = (x.z > 0.0f ? sp : sn) * x.z;
    o.w = (x.w > 0.0f ? sp : sn) * x.w;
    O[idx] = o;
}

extern "C" void kernel_launch(void* const* d_in, const int* in_sizes, int n_in,
                              void* d_out, int out_size) {
    const float* X  = (const float*)d_in[0];
    const float* w1 = (const float*)d_in[1];
    const float* w2 = (const float*)d_in[2];
    const float* w3 = (const float*)d_in[3];
    const float* w4 = (const float*)d_in[4];
    float* out = (float*)d_out;

    precompute_scales<<<1, 64>>>(w1, w2, w3, w4);

    dim3 grid((B4_ + 255) / 256, NP_);
    apply_scales<<<grid, 256>>>((const float4*)X, (float4*)out);
}

// round 5
// speedup vs baseline: 1.1303x; 1.1303x over previous
#include <cuda_runtime.h>

// Problem constants: NP=44 tiny MLPs, B=400000 batch.
#define NP_ 44
#define B_  400000
#define B4_ (B_ / 4)          // 100000 float4 per l
#define VPT 4                 // float4s per thread
#define TPB 256
#define CHUNK (TPB * VPT)     // 1024 float4 per block

// One fused kernel: each block recomputes the two collapsed-MLP scalars for
// its l (thread 0, weights hit L2 after first wave), broadcasts via smem,
// then streams its chunk with 4 independent float4 loads per thread (MLP=4).
//
// Collapse logic: input is scalar x, so every activation is coeff*x and the
// ReLU mask depends only on sign(x): keep positive coefficients when x>0,
// negative when x<0. out = (x>0 ? s_pos : s_neg) * x.
__global__ __launch_bounds__(TPB) void fused_mlp_stream(
    const float4* __restrict__ X, float4* __restrict__ O,
    const float* __restrict__ w1,   // (NP,4,1)
    const float* __restrict__ w2,   // (NP,8,4)
    const float* __restrict__ w3,   // (NP,4,8)
    const float* __restrict__ w4) { // (NP,1,4)

    __shared__ float s_scale[2];
    const int l = blockIdx.y;

    if (threadIdx.x == 0) {
        const float* W1 = w1 + l * 4;
        const float* W2 = w2 + l * 32;
        const float* W3 = w3 + l * 32;
        const float* W4 = w4 + l * 4;
        #pragma unroll
        for (int s = 0; s < 2; ++s) {
            const bool pos = (s == 0);
            float a[4];
            #pragma unroll
            for (int i = 0; i < 4; ++i) {
                float w = W1[i];
                a[i] = (pos ? (w > 0.0f) : (w < 0.0f)) ? w : 0.0f;
            }
            float b[8];
            #pragma unroll
            for (int j = 0; j < 8; ++j) {
                float t = 0.0f;
                #pragma unroll
                for (int i = 0; i < 4; ++i) t += W2[j * 4 + i] * a[i];
                b[j] = (pos ? (t > 0.0f) : (t < 0.0f)) ? t : 0.0f;
            }
            float c[4];
            #pragma unroll
            for (int i = 0; i < 4; ++i) {
                float t = 0.0f;
                #pragma unroll
                for (int j = 0; j < 8; ++j) t += W3[i * 8 + j] * b[j];
                c[i] = (pos ? (t > 0.0f) : (t < 0.0f)) ? t : 0.0f;
            }
            float out = 0.0f;
            #pragma unroll
            for (int i = 0; i < 4; ++i) out += W4[i] * c[i];
            s_scale[s] = out;
        }
    }
    __syncthreads();

    const float sp = s_scale[0];
    const float sn = s_scale[1];

    const long lbase = (long)l * B4_;
    const int base = blockIdx.x * CHUNK + threadIdx.x;

    // 4 independent loads issued back-to-back (MLP=4), then 4 stores.
    float4 x[VPT];
    bool ok[VPT];
    #pragma unroll
    for (int k = 0; k < VPT; ++k) {
        const int i = base + k * TPB;
        ok[k] = (i < B4_);
        if (ok[k]) x[k] = X[lbase + i];
    }
    #pragma unroll
    for (int k = 0; k < VPT; ++k) {
        if (ok[k]) {
            float4 v = x[k];
            float4 o;
            o.x = (v.x > 0.0f ? sp : sn) * v.x;
            o.y = (v.y > 0.0f ? sp : sn) * v.y;
            o.z = (v.z > 0.0f ? sp : sn) * v.z;
            o.w = (v.w > 0.0f ? sp : sn) * v.w;
            O[lbase + base + k * TPB] = o;
        }
    }
}

extern "C" void kernel_launch(void* const* d_in, const int* in_sizes, int n_in,
                              void* d_out, int out_size) {
    const float* X  = (const float*)d_in[0];
    const float* w1 = (const float*)d_in[1];
    const float* w2 = (const float*)d_in[2];
    const float* w3 = (const float*)d_in[3];
    const float* w4 = (const float*)d_in[4];
    float* out = (float*)d_out;

    dim3 grid((B4_ + CHUNK - 1) / CHUNK, NP_);   // (98, 44) = 4312 blocks
    fused_mlp_stream<<<grid, TPB>>>((const float4*)X, (float4*)out,
                                    w1, w2, w3, w4);
}

// round 7
// speedup vs baseline: 1.5158x; 1.3411x over previous
#include <cuda_runtime.h>

// Problem constants: NP=44 tiny MLPs, B=400000 batch.
#define NP_ 44
#define B_  400000
#define B4_ (B_ / 4)          // 100000 float4 per l
#define VPT 8                 // float4s per thread
#define TPB 256
#define CHUNK (TPB * VPT)     // 2048 float4 per block

// Fused kernel. Preamble: 72 threads load the block's l-weights in parallel
// into smem; 2 threads collapse the 1->4->8->4->1 ReLU MLP into the two
// sign-conditional scalars (mask depends only on sign(x) since input is
// scalar: out = (x>0 ? s_pos : s_neg) * x). Main: 8 front-batched float4
// loads per thread, evict-first stores to keep X resident in L2.
__global__ __launch_bounds__(TPB) void fused_mlp_stream(
    const float4* __restrict__ X, float4* __restrict__ O,
    const float* __restrict__ w1,   // (NP,4,1)
    const float* __restrict__ w2,   // (NP,8,4)
    const float* __restrict__ w3,   // (NP,4,8)
    const float* __restrict__ w4) { // (NP,1,4)

    __shared__ float sw[72];        // [0:4) w1, [4:36) w2, [36:68) w3, [68:72) w4
    __shared__ float s_scale[2];

    const int l = blockIdx.y;
    const int t = threadIdx.x;

    // Parallel weight fetch (one load per thread, lanes 0..71).
    if (t < 72) {
        float v;
        if      (t < 4)  v = w1[l * 4  + t];
        else if (t < 36) v = w2[l * 32 + (t - 4)];
        else if (t < 68) v = w3[l * 32 + (t - 36)];
        else             v = w4[l * 4  + (t - 68)];
        sw[t] = v;
    }
    __syncthreads();

    // Two threads compute the two collapsed scalars (s=0: x>0, s=1: x<0).
    if (t < 2) {
        const bool pos = (t == 0);
        const float* W1 = sw;
        const float* W2 = sw + 4;
        const float* W3 = sw + 36;
        const float* W4 = sw + 68;
        float a[4];
        #pragma unroll
        for (int i = 0; i < 4; ++i) {
            float w = W1[i];
            a[i] = (pos ? (w > 0.0f) : (w < 0.0f)) ? w : 0.0f;
        }
        float b[8];
        #pragma unroll
        for (int j = 0; j < 8; ++j) {
            float s = 0.0f;
            #pragma unroll
            for (int i = 0; i < 4; ++i) s += W2[j * 4 + i] * a[i];
            b[j] = (pos ? (s > 0.0f) : (s < 0.0f)) ? s : 0.0f;
        }
        float c[4];
        #pragma unroll
        for (int i = 0; i < 4; ++i) {
            float s = 0.0f;
            #pragma unroll
            for (int j = 0; j < 8; ++j) s += W3[i * 8 + j] * b[j];
            c[i] = (pos ? (s > 0.0f) : (s < 0.0f)) ? s : 0.0f;
        }
        float out = 0.0f;
        #pragma unroll
        for (int i = 0; i < 4; ++i) out += W4[i] * c[i];
        s_scale[t] = out;
    }
    __syncthreads();

    const float sp = s_scale[0];
    const float sn = s_scale[1];

    const long lbase = (long)l * B4_;
    const int base = blockIdx.x * CHUNK + t;

    // 8 independent front-batched loads (deep L1tex queue), then 8 stores.
    float4 x[VPT];
    bool ok[VPT];
    #pragma unroll
    for (int k = 0; k < VPT; ++k) {
        const int i = base + k * TPB;
        ok[k] = (i < B4_);
        if (ok[k]) x[k] = X[lbase + i];
    }
    #pragma unroll
    for (int k = 0; k < VPT; ++k) {
        if (ok[k]) {
            float4 v = x[k];
            float4 o;
            o.x = (v.x > 0.0f ? sp : sn) * v.x;
            o.y = (v.y > 0.0f ? sp : sn) * v.y;
            o.z = (v.z > 0.0f ? sp : sn) * v.z;
            o.w = (v.w > 0.0f ? sp : sn) * v.w;
            // Evict-first store: don't let write-once output displace X in L2.
            __stcs(&O[lbase + base + k * TPB], o);
        }
    }
}

extern "C" void kernel_launch(void* const* d_in, const int* in_sizes, int n_in,
                              void* d_out, int out_size) {
    const float* X  = (const float*)d_in[0];
    const float* w1 = (const float*)d_in[1];
    const float* w2 = (const float*)d_in[2];
    const float* w3 = (const float*)d_in[3];
    const float* w4 = (const float*)d_in[4];
    float* out = (float*)d_out;

    dim3 grid((B4_ + CHUNK - 1) / CHUNK, NP_);   // (49, 44) = 2156 blocks
    fused_mlp_stream<<<grid, TPB>>>((const float4*)X, (float4*)out,
                                    w1, w2, w3, w4);
}

// round 10
// speedup vs baseline: 1.5327x; 1.0111x over previous
#include <cuda_runtime.h>

// Problem constants: NP=44 tiny MLPs, B=400000 batch.
#define NP_  44
#define B_   400000
#define B4_  (B_ / 4)          // 100000 float4 per l  (= 32 * 3125)
#define TPB  160               // 5 warps
#define VPT  5                 // float4s in flight per iteration
#define ITER 5                 // iterations per block
#define STEP (TPB * VPT)       // 800 float4 per iteration
#define CHUNK (STEP * ITER)    // 4000 float4 per block; 100000/4000 = 25 exact

// Fused kernel. Preamble: 72 threads load this l's weights in parallel into
// smem; 2 threads collapse the 1->4->8->4->1 ReLU MLP into two scalars
// (input is scalar per element, so the ReLU mask depends only on sign(x):
// out = (x>0 ? s_pos : s_neg) * x). Main loop: 5 iterations of 5
// front-batched float4 loads, compute, evict-first stores. Exact partition:
// no bounds checks anywhere.
__global__ __launch_bounds__(TPB, 10) void fused_mlp_stream(
    const float4* __restrict__ X, float4* __restrict__ O,
    const float* __restrict__ w1,   // (NP,4,1)
    const float* __restrict__ w2,   // (NP,8,4)
    const float* __restrict__ w3,   // (NP,4,8)
    const float* __restrict__ w4) { // (NP,1,4)

    __shared__ float sw[72];        // [0:4) w1, [4:36) w2, [36:68) w3, [68:72) w4
    __shared__ float s_scale[2];

    const int l = blockIdx.y;
    const int t = threadIdx.x;

    // Parallel weight fetch (lanes 0..71, one load each).
    if (t < 72) {
        float v;
        if      (t < 4)  v = w1[l * 4  + t];
        else if (t < 36) v = w2[l * 32 + (t - 4)];
        else if (t < 68) v = w3[l * 32 + (t - 36)];
        else             v = w4[l * 4  + (t - 68)];
        sw[t] = v;
    }
    __syncthreads();

    // Two threads compute the two collapsed scalars (t=0: x>0, t=1: x<0).
    if (t < 2) {
        const bool pos = (t == 0);
        const float* W1 = sw;
        const float* W2 = sw + 4;
        const float* W3 = sw + 36;
        const float* W4 = sw + 68;
        float a[4];
        #pragma unroll
        for (int i = 0; i < 4; ++i) {
            float w = W1[i];
            a[i] = (pos ? (w > 0.0f) : (w < 0.0f)) ? w : 0.0f;
        }
        float b[8];
        #pragma unroll
        for (int j = 0; j < 8; ++j) {
            float s = 0.0f;
            #pragma unroll
            for (int i = 0; i < 4; ++i) s += W2[j * 4 + i] * a[i];
            b[j] = (pos ? (s > 0.0f) : (s < 0.0f)) ? s : 0.0f;
        }
        float c[4];
        #pragma unroll
        for (int i = 0; i < 4; ++i) {
            float s = 0.0f;
            #pragma unroll
            for (int j = 0; j < 8; ++j) s += W3[i * 8 + j] * b[j];
            c[i] = (pos ? (s > 0.0f) : (s < 0.0f)) ? s : 0.0f;
        }
        float out = 0.0f;
        #pragma unroll
        for (int i = 0; i < 4; ++i) out += W4[i] * c[i];
        s_scale[t] = out;
    }
    __syncthreads();

    const float sp = s_scale[0];
    const float sn = s_scale[1];

    // Base of this block's exact 4000-float4 region within its l.
    const float4* __restrict__ xi = X + (long)l * B4_ + blockIdx.x * CHUNK + t;
    float4*       __restrict__ oi = O + (long)l * B4_ + blockIdx.x * CHUNK + t;

    #pragma unroll
    for (int it = 0; it < ITER; ++it) {
        float4 x[VPT];
        #pragma unroll
        for (int k = 0; k < VPT; ++k)
            x[k] = xi[k * TPB];
        #pragma unroll
        for (int k = 0; k < VPT; ++k) {
            float4 v = x[k];
            float4 o;
            o.x = (v.x > 0.0f ? sp : sn) * v.x;
            o.y = (v.y > 0.0f ? sp : sn) * v.y;
            o.z = (v.z > 0.0f ? sp : sn) * v.z;
            o.w = (v.w > 0.0f ? sp : sn) * v.w;
            // Evict-first store: write-once output must not displace X in L2.
            __stcs(&oi[k * TPB], o);
        }
        xi += STEP;
        oi += STEP;
    }
}

extern "C" void kernel_launch(void* const* d_in, const int* in_sizes, int n_in,
                              void* d_out, int out_size) {
    const float* X  = (const float*)d_in[0];
    const float* w1 = (const float*)d_in[1];
    const float* w2 = (const float*)d_in[2];
    const float* w3 = (const float*)d_in[3];
    const float* w4 = (const float*)d_in[4];
    float* out = (float*)d_out;

    dim3 grid(B4_ / CHUNK, NP_);   // (25, 44) = 1100 blocks, exact
    fused_mlp_stream<<<grid, TPB>>>((const float4*)X, (float4*)out,
                                    w1, w2, w3, w4);
}